// round 15
// baseline (speedup 1.0000x reference)
#include <cuda_runtime.h>
#include <cuda_bf16.h>
#include <cstdint>
#include <cstdio>

#define NN 50000
#define NE 400000
#define HID 256
#define EDIM 768
#define NL 6

// ---------------- scratch ----------------
__device__ float g_hl[NN * HID];          // per-layer h @ Wc (GEMM out)
__device__ float g_hn[NN * HID];          // scatter accumulator (unnormalized)
__device__ float g_ee[NL * NE];
__device__ float g_ea[NE];                // leaky-relu alpha per edge
__device__ float g_s[NN];
__device__ float g_d[NN];
__device__ float g_mx[NN];
__device__ float g_dn[NN];
__device__ float g_Ve[NL * EDIM];
__device__ float g_ws[NL * HID];          // Wslot[l] @ a_s[l]
__device__ float g_wd[NL * HID];          // Wslot[l] @ a_d[l]
__device__ float g_W12[HID * HID];
__device__ float g_W012[HID * HID];
__device__ float g_Wsum[HID * HID];
__device__ __nv_bfloat16 g_Ahi[NN * HID];
__device__ __nv_bfloat16 g_Alo[NN * HID];
__device__ __nv_bfloat16 g_Bthi[7 * HID * HID];
__device__ __nv_bfloat16 g_Btlo[7 * HID * HID];

__device__ __forceinline__ void atomicMaxF(float* addr, float val) {
    if (val >= 0.f) atomicMax((int*)addr, __float_as_int(val));
    else            atomicMin((unsigned int*)addr, __float_as_uint(val));
}

// ---------------- fp32 SGEMM (weight precompute only, M=256) ----------------
__global__ __launch_bounds__(256) void sgemm128(
    const float* __restrict__ A, const float* __restrict__ B,
    float* __restrict__ C, int M)
{
    const int N = HID, K = HID;
    __shared__ float As[8][128];
    __shared__ float Bs[8][128];
    int tid = threadIdx.x;
    int bn = blockIdx.x * 128;
    int bm = blockIdx.y * 128;
    int arow = tid >> 1;
    int acol = (tid & 1) << 2;
    int brow = tid >> 5;
    int bcol = (tid & 31) << 2;
    int tx = tid & 15;
    int ty = tid >> 4;
    int grow = bm + arow;

    float acc[8][8];
#pragma unroll
    for (int i = 0; i < 8; i++)
#pragma unroll
        for (int j = 0; j < 8; j++) acc[i][j] = 0.f;

    for (int k0 = 0; k0 < K; k0 += 8) {
        float4 av = make_float4(0.f, 0.f, 0.f, 0.f);
        if (grow < M) av = *(const float4*)(A + (size_t)grow * K + k0 + acol);
        As[acol + 0][arow] = av.x;
        As[acol + 1][arow] = av.y;
        As[acol + 2][arow] = av.z;
        As[acol + 3][arow] = av.w;
        *(float4*)&Bs[brow][bcol] =
            *(const float4*)(B + (size_t)(k0 + brow) * N + bn + bcol);
        __syncthreads();
#pragma unroll
        for (int kk = 0; kk < 8; kk++) {
            float ra[8], rb[8];
            *(float4*)&ra[0] = *(const float4*)&As[kk][ty * 8];
            *(float4*)&ra[4] = *(const float4*)&As[kk][ty * 8 + 4];
            *(float4*)&rb[0] = *(const float4*)&Bs[kk][tx * 8];
            *(float4*)&rb[4] = *(const float4*)&Bs[kk][tx * 8 + 4];
#pragma unroll
            for (int i = 0; i < 8; i++)
#pragma unroll
                for (int j = 0; j < 8; j++)
                    acc[i][j] += ra[i] * rb[j];
        }
        __syncthreads();
    }
#pragma unroll
    for (int i = 0; i < 8; i++) {
        int r = bm + ty * 8 + i;
        if (r < M) {
            *(float4*)(C + (size_t)r * N + bn + tx * 8) =
                make_float4(acc[i][0], acc[i][1], acc[i][2], acc[i][3]);
            *(float4*)(C + (size_t)r * N + bn + tx * 8 + 4) =
                make_float4(acc[i][4], acc[i][5], acc[i][6], acc[i][7]);
        }
    }
}

// ---------------- bf16x3 tensor-core GEMM, preconverted operands ----------------
#define ASTR 40
#define STG  20480
#define AOLO 5120
#define AOBH 10240
#define AOBL 15360

__device__ __forceinline__ void mma16816(float* c, const uint32_t* a, const uint32_t* b) {
    asm volatile(
        "mma.sync.aligned.m16n8k16.row.col.f32.bf16.bf16.f32 "
        "{%0,%1,%2,%3}, {%4,%5,%6,%7}, {%8,%9}, {%0,%1,%2,%3};\n"
        : "+f"(c[0]), "+f"(c[1]), "+f"(c[2]), "+f"(c[3])
        : "r"(a[0]), "r"(a[1]), "r"(a[2]), "r"(a[3]), "r"(b[0]), "r"(b[1]));
}

__global__ __launch_bounds__(256) void mma_gemm2(
    const __nv_bfloat16* __restrict__ Ahi, const __nv_bfloat16* __restrict__ Alo,
    const __nv_bfloat16* __restrict__ Bhi, const __nv_bfloat16* __restrict__ Blo,
    float* __restrict__ C, int M)
{
    extern __shared__ __nv_bfloat16 sm[];
    const int tid = threadIdx.x;
    const int lane = tid & 31, wid = tid >> 5;
    const int warp_m = wid & 1, warp_n = wid >> 1;
    const int g = lane >> 2, t = lane & 3;
    const int bm = blockIdx.y * 128, bn = blockIdx.x * 128;

    float acc[4][4][4];
#pragma unroll
    for (int i = 0; i < 4; i++)
#pragma unroll
        for (int j = 0; j < 4; j++)
#pragma unroll
            for (int k = 0; k < 4; k++) acc[i][j][k] = 0.f;

    auto load_stage = [&](int k0, int s) {
        uint32_t base = (uint32_t)__cvta_generic_to_shared(sm + (size_t)s * STG);
#pragma unroll
        for (int i = 0; i < 2; i++) {
            int c = tid + 256 * i;
            int row = c >> 2, cc = c & 3;
            uint32_t doff = (uint32_t)(row * ASTR + cc * 8) * 2;
            size_t goff = (size_t)(bm + row) * HID + k0 + cc * 8;
            int szA = (bm + row) < M ? 16 : 0;
            asm volatile("cp.async.ca.shared.global [%0], [%1], 16, %2;\n"
                         :: "r"(base + doff), "l"(Ahi + goff), "r"(szA));
            asm volatile("cp.async.ca.shared.global [%0], [%1], 16, %2;\n"
                         :: "r"(base + AOLO * 2 + doff), "l"(Alo + goff), "r"(szA));
            size_t boff = (size_t)(bn + row) * HID + k0 + cc * 8;
            asm volatile("cp.async.ca.shared.global [%0], [%1], 16;\n"
                         :: "r"(base + AOBH * 2 + doff), "l"(Bhi + boff));
            asm volatile("cp.async.ca.shared.global [%0], [%1], 16;\n"
                         :: "r"(base + AOBL * 2 + doff), "l"(Blo + boff));
        }
        asm volatile("cp.async.commit_group;\n");
    };

    load_stage(0, 0);
    for (int k0i = 0; k0i < 8; k0i++) {
        if (k0i < 7) load_stage((k0i + 1) * 32, (k0i + 1) & 1);
        if (k0i < 7) asm volatile("cp.async.wait_group 1;\n");
        else         asm volatile("cp.async.wait_group 0;\n");
        __syncthreads();

        const __nv_bfloat16* sAhi = sm + (size_t)(k0i & 1) * STG;
        const __nv_bfloat16* sAlo = sAhi + AOLO;
        const __nv_bfloat16* sBhi = sAhi + AOBH;
        const __nv_bfloat16* sBlo = sAhi + AOBL;

#pragma unroll
        for (int ks = 0; ks < 32; ks += 16) {
            uint32_t afh[4][4], afl[4][4], bfh[4][2], bfl[4][2];
#pragma unroll
            for (int mt = 0; mt < 4; mt++) {
                int base = (warp_m * 64 + mt * 16 + g) * ASTR + ks + 2 * t;
                afh[mt][0] = *(const uint32_t*)&sAhi[base];
                afh[mt][1] = *(const uint32_t*)&sAhi[base + 8 * ASTR];
                afh[mt][2] = *(const uint32_t*)&sAhi[base + 8];
                afh[mt][3] = *(const uint32_t*)&sAhi[base + 8 * ASTR + 8];
                afl[mt][0] = *(const uint32_t*)&sAlo[base];
                afl[mt][1] = *(const uint32_t*)&sAlo[base + 8 * ASTR];
                afl[mt][2] = *(const uint32_t*)&sAlo[base + 8];
                afl[mt][3] = *(const uint32_t*)&sAlo[base + 8 * ASTR + 8];
            }
#pragma unroll
            for (int nt = 0; nt < 4; nt++) {
                int base = (warp_n * 32 + nt * 8 + g) * ASTR + ks + 2 * t;
                bfh[nt][0] = *(const uint32_t*)&sBhi[base];
                bfh[nt][1] = *(const uint32_t*)&sBhi[base + 8];
                bfl[nt][0] = *(const uint32_t*)&sBlo[base];
                bfl[nt][1] = *(const uint32_t*)&sBlo[base + 8];
            }
#pragma unroll
            for (int mt = 0; mt < 4; mt++)
#pragma unroll
                for (int nt = 0; nt < 4; nt++) {
                    mma16816(acc[mt][nt], afh[mt], bfh[nt]);
                    mma16816(acc[mt][nt], afh[mt], bfl[nt]);
                    mma16816(acc[mt][nt], afl[mt], bfh[nt]);
                }
        }
        __syncthreads();
    }

#pragma unroll
    for (int mt = 0; mt < 4; mt++) {
        int row = bm + warp_m * 64 + mt * 16 + g;
#pragma unroll
        for (int nt = 0; nt < 4; nt++) {
            int col = bn + warp_n * 32 + nt * 8 + 2 * t;
            if (row < M)
                *(float2*)(C + (size_t)row * HID + col) =
                    make_float2(acc[mt][nt][0], acc[mt][nt][1]);
            if (row + 8 < M)
                *(float2*)(C + (size_t)(row + 8) * HID + col) =
                    make_float2(acc[mt][nt][2], acc[mt][nt][3]);
        }
    }
}

// ---------------- fused per-node finalize/split/prep: warp per node ----------
// h = hn/(dn+eps) [+bias] [relu] -> split bf16 Ahi/Alo
// s = h . ws, d = h . wd (for next layer's attention), if ws != null
// re-zero hzero row, reset mx/dn for next scatter.
__global__ __launch_bounds__(256) void split_nd(
    const float* __restrict__ hn, const float* __restrict__ dnv,
    const float* __restrict__ b, int relu,
    const float* __restrict__ ws, const float* __restrict__ wd,
    __nv_bfloat16* __restrict__ hi, __nv_bfloat16* __restrict__ lo,
    float* __restrict__ s, float* __restrict__ d,
    float* __restrict__ hzero, float* __restrict__ mx, float* __restrict__ dn_out)
{
    int w = (blockIdx.x * blockDim.x + threadIdx.x) >> 5;
    int lane = threadIdx.x & 31;
    if (w >= NN) return;
    float inv = 1.f;
    if (dnv) inv = 1.f / (dnv[w] + 1e-16f);
    const float4* src = (const float4*)hn + (size_t)w * 64;
    float ss = 0.f, dd = 0.f;
#pragma unroll
    for (int i = 0; i < 2; i++) {
        int p = lane + 32 * i;
        float4 v = src[p];
        v.x *= inv; v.y *= inv; v.z *= inv; v.w *= inv;
        if (b) {
            float4 bb = ((const float4*)b)[p];
            v.x += bb.x; v.y += bb.y; v.z += bb.z; v.w += bb.w;
        }
        if (relu) {
            v.x = fmaxf(v.x, 0.f); v.y = fmaxf(v.y, 0.f);
            v.z = fmaxf(v.z, 0.f); v.w = fmaxf(v.w, 0.f);
        }
        if (ws) {
            float4 a = ((const float4*)ws)[p];
            float4 e = ((const float4*)wd)[p];
            ss += v.x * a.x + v.y * a.y + v.z * a.z + v.w * a.w;
            dd += v.x * e.x + v.y * e.y + v.z * e.z + v.w * e.w;
        }
        float vv[4] = {v.x, v.y, v.z, v.w};
        __nv_bfloat16 h4[4], l4[4];
#pragma unroll
        for (int j = 0; j < 4; j++) {
            h4[j] = __float2bfloat16_rn(vv[j]);
            l4[j] = __float2bfloat16_rn(vv[j] - __bfloat162float(h4[j]));
        }
        ((uint2*)hi)[(size_t)w * 64 + p] = *(uint2*)h4;
        ((uint2*)lo)[(size_t)w * 64 + p] = *(uint2*)l4;
    }
    if (hzero) {
        float4 z = make_float4(0.f, 0.f, 0.f, 0.f);
        ((float4*)hzero)[(size_t)w * 64 + lane]      = z;
        ((float4*)hzero)[(size_t)w * 64 + 32 + lane] = z;
    }
    if (ws) {
#pragma unroll
        for (int o = 16; o; o >>= 1) {
            ss += __shfl_xor_sync(~0u, ss, o);
            dd += __shfl_xor_sync(~0u, dd, o);
        }
        if (!lane) {
            s[w] = ss; d[w] = dd;
            mx[w] = -1e30f; dn_out[w] = 0.f;
        }
    }
}

// ---------------- weight-side precompute ----------------
__global__ void split_W(const float* __restrict__ W012, const float* __restrict__ Wc,
                        const float* __restrict__ Wsum,
                        __nv_bfloat16* __restrict__ hi, __nv_bfloat16* __restrict__ lo) {
    int i = blockIdx.x * blockDim.x + threadIdx.x;
    if (i >= 7 * HID * HID) return;
    int slot = i >> 16, r = i & 65535;
    int n = r >> 8, k = r & 255;
    const float* src = (slot == 0) ? W012
                     : (slot <= 5) ? Wc + (size_t)slot * HID * HID
                                   : Wsum;
    float v = src[k * HID + n];
    __nv_bfloat16 h = __float2bfloat16_rn(v);
    hi[i] = h;
    lo[i] = __float2bfloat16_rn(v - __bfloat162float(h));
}

__global__ void wsum_kernel(const float* __restrict__ W3, float* __restrict__ Wsum) {
    int i = blockIdx.x * blockDim.x + threadIdx.x;
    if (i < HID * HID) Wsum[i] = W3[i] + W3[i + HID * HID];
}

// ws[l][k] = Wslot[l][k,:] . a_s[l],  wd likewise (Wslot0 = W012)
__global__ void compute_wsd(const float* __restrict__ W012, const float* __restrict__ Wc,
                            const float* __restrict__ a_s, const float* __restrict__ a_d,
                            float* __restrict__ ws, float* __restrict__ wd) {
    int warp = (blockIdx.x * blockDim.x + threadIdx.x) >> 5;
    int lane = threadIdx.x & 31;
    if (warp >= NL * HID) return;
    int l = warp >> 8, k = warp & 255;
    const float* W = (l == 0) ? W012 : Wc + (size_t)l * HID * HID;
    const float4* row = (const float4*)(W + (size_t)k * HID);
    const float4* as4 = (const float4*)(a_s + (size_t)l * HID);
    const float4* ad4 = (const float4*)(a_d + (size_t)l * HID);
    float ss = 0.f, dd = 0.f;
#pragma unroll
    for (int i = 0; i < 2; i++) {
        int p = lane + 32 * i;
        float4 v = row[p];
        float4 a = as4[p];
        float4 e = ad4[p];
        ss += v.x * a.x + v.y * a.y + v.z * a.z + v.w * a.w;
        dd += v.x * e.x + v.y * e.y + v.z * e.z + v.w * e.w;
    }
#pragma unroll
    for (int o = 16; o; o >>= 1) {
        ss += __shfl_xor_sync(~0u, ss, o);
        dd += __shfl_xor_sync(~0u, dd, o);
    }
    if (!lane) { ws[l * HID + k] = ss; wd[l * HID + k] = dd; }
}

__global__ void compute_Ve(const float* __restrict__ We, const float* __restrict__ a_e,
                           float* __restrict__ Ve) {
    int w = (blockIdx.x * blockDim.x + threadIdx.x) >> 5;
    int lane = threadIdx.x & 31;
    if (w >= NL * EDIM) return;
    int l = w / EDIM, j = w % EDIM;
    const float4* wr = (const float4*)(We + ((size_t)l * EDIM + j) * HID);
    const float4* ar = (const float4*)(a_e + (size_t)l * HID);
    float s = 0.f;
#pragma unroll
    for (int i = 0; i < 2; i++) {
        float4 x = wr[lane + 32 * i];
        float4 y = ar[lane + 32 * i];
        s += x.x * y.x + x.y * y.y + x.z * y.z + x.w * y.w;
    }
#pragma unroll
    for (int o = 16; o; o >>= 1) s += __shfl_xor_sync(~0u, s, o);
    if (!lane) Ve[l * EDIM + j] = s;
}

// edge logits: one warp per 4 consecutive edges — sVe smem reads amortized 4x.
__global__ __launch_bounds__(256) void edge_dots4(const float* __restrict__ edge_attr,
                                                  float* __restrict__ out) {
    __shared__ float4 sVe[NL][EDIM / 4];   // 18 KB
    for (int i = threadIdx.x; i < NL * EDIM / 4; i += blockDim.x)
        ((float4*)sVe)[i] = ((const float4*)g_Ve)[i];
    __syncthreads();
    int w = (blockIdx.x * blockDim.x + threadIdx.x) >> 5;
    int lane = threadIdx.x & 31;
    int e0 = w * 4;
    if (e0 >= NE) return;
    const float4* row = (const float4*)edge_attr;

    float acc[NL][4];
#pragma unroll
    for (int l = 0; l < NL; l++)
#pragma unroll
        for (int j = 0; j < 4; j++) acc[l][j] = 0.f;

#pragma unroll
    for (int i = 0; i < 6; i++) {
        int p = lane + 32 * i;
        float4 v0 = row[(size_t)(e0 + 0) * (EDIM / 4) + p];
        float4 v1 = row[(size_t)(e0 + 1) * (EDIM / 4) + p];
        float4 v2 = row[(size_t)(e0 + 2) * (EDIM / 4) + p];
        float4 v3 = row[(size_t)(e0 + 3) * (EDIM / 4) + p];
#pragma unroll
        for (int l = 0; l < NL; l++) {
            float4 u = sVe[l][p];
            acc[l][0] += v0.x * u.x + v0.y * u.y + v0.z * u.z + v0.w * u.w;
            acc[l][1] += v1.x * u.x + v1.y * u.y + v1.z * u.z + v1.w * u.w;
            acc[l][2] += v2.x * u.x + v2.y * u.y + v2.z * u.z + v2.w * u.w;
            acc[l][3] += v3.x * u.x + v3.y * u.y + v3.z * u.z + v3.w * u.w;
        }
    }
#pragma unroll
    for (int l = 0; l < NL; l++)
#pragma unroll
        for (int j = 0; j < 4; j++) {
            float a = acc[l][j];
#pragma unroll
            for (int o = 16; o; o >>= 1) a += __shfl_xor_sync(~0u, a, o);
            if (!lane) out[(size_t)l * NE + e0 + j] = a;
        }
}

__global__ void alpha_max(const int* __restrict__ ei, const float* __restrict__ s,
                          const float* __restrict__ d, const float* __restrict__ ee,
                          float* __restrict__ alpha, float* __restrict__ mx) {
    int e = blockIdx.x * blockDim.x + threadIdx.x;
    if (e >= NE) return;
    int src = ei[e];
    int dst = ei[NE + e];
    float a = s[src] + d[dst] + ee[e];
    a = a > 0.f ? a : 0.2f * a;
    alpha[e] = a;
    atomicMaxF(&mx[dst], a);
}

// fused: ea = exp(alpha - mx[dst]); dn[dst] += ea; out[dst] += ea * h[src]
__global__ void scatter_ea(const int* __restrict__ ei, const float* __restrict__ h,
                           const float* __restrict__ alpha, const float* __restrict__ mx,
                           float* __restrict__ dn, float* __restrict__ out) {
    int w = (blockIdx.x * blockDim.x + threadIdx.x) >> 5;
    int lane = threadIdx.x & 31;
    if (w >= NE) return;
    int src = ei[w];
    int dst = ei[NE + w];
    float eaV = __expf(alpha[w] - mx[dst]);
    if (!lane) atomicAdd(&dn[dst], eaV);
    const float4* hs = (const float4*)(h + (size_t)src * HID);
    float* ob = out + (size_t)dst * HID;
#pragma unroll
    for (int i = 0; i < 2; i++) {
        int p = lane + 32 * i;
        float4 v = hs[p];
        float x = v.x * eaV, y = v.y * eaV, z = v.z * eaV, u = v.w * eaV;
        asm volatile("red.global.add.v4.f32 [%0], {%1,%2,%3,%4};"
                     :: "l"(ob + p * 4), "f"(x), "f"(y), "f"(z), "f"(u)
                     : "memory");
    }
}

// ---------------- launch ----------------
extern "C" void kernel_launch(void* const* d_in, const int* in_sizes, int n_in,
                              void* d_out, int out_size) {
    const float* x    = (const float*)d_in[0];
    const int*   ei   = (const int*)d_in[1];
    const float* eatt = (const float*)d_in[2];
    const float* W1   = (const float*)d_in[3];
    const float* W2   = (const float*)d_in[4];
    const float* Wc   = (const float*)d_in[5];
    const float* We   = (const float*)d_in[6];
    const float* a_s  = (const float*)d_in[7];
    const float* a_d  = (const float*)d_in[8];
    const float* a_e  = (const float*)d_in[9];
    const float* bias = (const float*)d_in[10];
    const float* W3   = (const float*)d_in[11];
    float*       out  = (float*)d_out;

    float *p_hl, *p_hn, *p_ee, *p_ea, *p_s, *p_d, *p_mx, *p_dn, *p_Ve;
    float *p_ws, *p_wd, *p_W12, *p_W012, *p_Ws;
    __nv_bfloat16 *p_Ahi, *p_Alo, *p_Bthi, *p_Btlo;
    cudaGetSymbolAddress((void**)&p_hl, g_hl);
    cudaGetSymbolAddress((void**)&p_hn, g_hn);
    cudaGetSymbolAddress((void**)&p_ee, g_ee);
    cudaGetSymbolAddress((void**)&p_ea, g_ea);
    cudaGetSymbolAddress((void**)&p_s, g_s);
    cudaGetSymbolAddress((void**)&p_d, g_d);
    cudaGetSymbolAddress((void**)&p_mx, g_mx);
    cudaGetSymbolAddress((void**)&p_dn, g_dn);
    cudaGetSymbolAddress((void**)&p_Ve, g_Ve);
    cudaGetSymbolAddress((void**)&p_ws, g_ws);
    cudaGetSymbolAddress((void**)&p_wd, g_wd);
    cudaGetSymbolAddress((void**)&p_W12, g_W12);
    cudaGetSymbolAddress((void**)&p_W012, g_W012);
    cudaGetSymbolAddress((void**)&p_Ws, g_Wsum);
    cudaGetSymbolAddress((void**)&p_Ahi, g_Ahi);
    cudaGetSymbolAddress((void**)&p_Alo, g_Alo);
    cudaGetSymbolAddress((void**)&p_Bthi, g_Bthi);
    cudaGetSymbolAddress((void**)&p_Btlo, g_Btlo);

    cudaFuncSetAttribute(mma_gemm2, cudaFuncAttributeMaxDynamicSharedMemorySize,
                         2 * STG * (int)sizeof(__nv_bfloat16));
    const size_t smem_sz = 2 * STG * sizeof(__nv_bfloat16);

    const int MBY = (NN + 127) / 128;
    const dim3 gemm_grid(2, MBY);
    const int NODE_W = (NN * 32 + 255) / 256;

    // ---- one-time precompute ----
    sgemm128<<<dim3(2, 2), 256>>>(W1, W2, p_W12, HID);
    sgemm128<<<dim3(2, 2), 256>>>(p_W12, Wc, p_W012, HID);
    wsum_kernel<<<(HID * HID + 255) / 256, 256>>>(W3, p_Ws);
    split_W<<<(7 * HID * HID + 255) / 256, 256>>>(p_W012, Wc, p_Ws, p_Bthi, p_Btlo);
    compute_wsd<<<(NL * HID * 32 + 255) / 256, 256>>>(p_W012, Wc, a_s, a_d, p_ws, p_wd);
    compute_Ve<<<(NL * EDIM * 32 + 255) / 256, 256>>>(We, a_e, p_Ve);
    edge_dots4<<<((NE / 4) * 32 + 255) / 256, 256>>>(eatt, p_ee);

    // initial: A = split(x); s,d for layer 0; zero hn; init mx/dn
    split_nd<<<NODE_W, 256>>>(x, nullptr, nullptr, 0, p_ws, p_wd,
                              p_Ahi, p_Alo, p_s, p_d, p_hn, p_mx, p_dn);

    for (int l = 0; l < NL; l++) {
        mma_gemm2<<<gemm_grid, 256, smem_sz>>>(
            p_Ahi, p_Alo,
            p_Bthi + (size_t)l * HID * HID, p_Btlo + (size_t)l * HID * HID,
            p_hl, NN);
        alpha_max<<<(NE + 255) / 256, 256>>>(ei, p_s, p_d, p_ee + (size_t)l * NE,
                                             p_ea, p_mx);
        scatter_ea<<<(NE * 32 + 255) / 256, 256>>>(ei, p_hl, p_ea, p_mx, p_dn, p_hn);
        // finalize layer l; prepare s,d/mx/dn/hn for layer l+1 (skip attn prep after last)
        int last = (l == NL - 1);
        split_nd<<<NODE_W, 256>>>(p_hn, p_dn, bias + (size_t)l * HID, last,
                                  last ? nullptr : p_ws + (size_t)(l + 1) * HID,
                                  last ? nullptr : p_wd + (size_t)(l + 1) * HID,
                                  p_Ahi, p_Alo, p_s, p_d,
                                  last ? nullptr : p_hn, p_mx, p_dn);
    }

    // out = relu(h) @ (W3a + W3b)
    mma_gemm2<<<gemm_grid, 256, smem_sz>>>(
        p_Ahi, p_Alo,
        p_Bthi + (size_t)6 * HID * HID, p_Btlo + (size_t)6 * HID * HID,
        out, NN);
}

// round 16
// speedup vs baseline: 1.4734x; 1.4734x over previous
#include <cuda_runtime.h>
#include <cuda_bf16.h>
#include <cstdint>
#include <cstdio>

#define NN 50000
#define NE 400000
#define HID 256
#define EDIM 768
#define NL 6

// ---------------- scratch ----------------
__device__ float g_hl[NN * HID];          // per-layer h @ Wc (GEMM out)
__device__ float g_hn[NN * HID];          // scatter accumulator (unnormalized)
__device__ float g_ee[NL * NE];
__device__ float g_ea[NE];                // leaky-relu alpha per edge
__device__ float g_s[NN];
__device__ float g_d[NN];
__device__ float g_mx[NN];
__device__ float g_dn[NN];
__device__ float g_Ve[NL * EDIM];
__device__ float g_ws[NL * HID];          // Wslot[l] @ a_s[l]
__device__ float g_wd[NL * HID];          // Wslot[l] @ a_d[l]
__device__ float g_W12[HID * HID];
__device__ float g_W012[HID * HID];
__device__ float g_Wsum[HID * HID];
__device__ __nv_bfloat16 g_Ahi[NN * HID];
__device__ __nv_bfloat16 g_Alo[NN * HID];
__device__ __nv_bfloat16 g_Bthi[7 * HID * HID];
__device__ __nv_bfloat16 g_Btlo[7 * HID * HID];

__device__ __forceinline__ void atomicMaxF(float* addr, float val) {
    if (val >= 0.f) atomicMax((int*)addr, __float_as_int(val));
    else            atomicMin((unsigned int*)addr, __float_as_uint(val));
}

// ---------------- fp32 SGEMM (weight precompute only, M=256) ----------------
__global__ __launch_bounds__(256) void sgemm128(
    const float* __restrict__ A, const float* __restrict__ B,
    float* __restrict__ C, int M)
{
    const int N = HID, K = HID;
    __shared__ float As[8][128];
    __shared__ float Bs[8][128];
    int tid = threadIdx.x;
    int bn = blockIdx.x * 128;
    int bm = blockIdx.y * 128;
    int arow = tid >> 1;
    int acol = (tid & 1) << 2;
    int brow = tid >> 5;
    int bcol = (tid & 31) << 2;
    int tx = tid & 15;
    int ty = tid >> 4;
    int grow = bm + arow;

    float acc[8][8];
#pragma unroll
    for (int i = 0; i < 8; i++)
#pragma unroll
        for (int j = 0; j < 8; j++) acc[i][j] = 0.f;

    for (int k0 = 0; k0 < K; k0 += 8) {
        float4 av = make_float4(0.f, 0.f, 0.f, 0.f);
        if (grow < M) av = *(const float4*)(A + (size_t)grow * K + k0 + acol);
        As[acol + 0][arow] = av.x;
        As[acol + 1][arow] = av.y;
        As[acol + 2][arow] = av.z;
        As[acol + 3][arow] = av.w;
        *(float4*)&Bs[brow][bcol] =
            *(const float4*)(B + (size_t)(k0 + brow) * N + bn + bcol);
        __syncthreads();
#pragma unroll
        for (int kk = 0; kk < 8; kk++) {
            float ra[8], rb[8];
            *(float4*)&ra[0] = *(const float4*)&As[kk][ty * 8];
            *(float4*)&ra[4] = *(const float4*)&As[kk][ty * 8 + 4];
            *(float4*)&rb[0] = *(const float4*)&Bs[kk][tx * 8];
            *(float4*)&rb[4] = *(const float4*)&Bs[kk][tx * 8 + 4];
#pragma unroll
            for (int i = 0; i < 8; i++)
#pragma unroll
                for (int j = 0; j < 8; j++)
                    acc[i][j] += ra[i] * rb[j];
        }
        __syncthreads();
    }
#pragma unroll
    for (int i = 0; i < 8; i++) {
        int r = bm + ty * 8 + i;
        if (r < M) {
            *(float4*)(C + (size_t)r * N + bn + tx * 8) =
                make_float4(acc[i][0], acc[i][1], acc[i][2], acc[i][3]);
            *(float4*)(C + (size_t)r * N + bn + tx * 8 + 4) =
                make_float4(acc[i][4], acc[i][5], acc[i][6], acc[i][7]);
        }
    }
}

// ---------------- bf16x3 tensor-core GEMM, preconverted operands ----------------
#define ASTR 40
#define STG  20480
#define AOLO 5120
#define AOBH 10240
#define AOBL 15360

__device__ __forceinline__ void mma16816(float* c, const uint32_t* a, const uint32_t* b) {
    asm volatile(
        "mma.sync.aligned.m16n8k16.row.col.f32.bf16.bf16.f32 "
        "{%0,%1,%2,%3}, {%4,%5,%6,%7}, {%8,%9}, {%0,%1,%2,%3};\n"
        : "+f"(c[0]), "+f"(c[1]), "+f"(c[2]), "+f"(c[3])
        : "r"(a[0]), "r"(a[1]), "r"(a[2]), "r"(a[3]), "r"(b[0]), "r"(b[1]));
}

__global__ __launch_bounds__(256) void mma_gemm2(
    const __nv_bfloat16* __restrict__ Ahi, const __nv_bfloat16* __restrict__ Alo,
    const __nv_bfloat16* __restrict__ Bhi, const __nv_bfloat16* __restrict__ Blo,
    float* __restrict__ C, int M)
{
    extern __shared__ __nv_bfloat16 sm[];
    const int tid = threadIdx.x;
    const int lane = tid & 31, wid = tid >> 5;
    const int warp_m = wid & 1, warp_n = wid >> 1;
    const int g = lane >> 2, t = lane & 3;
    const int bm = blockIdx.y * 128, bn = blockIdx.x * 128;

    float acc[4][4][4];
#pragma unroll
    for (int i = 0; i < 4; i++)
#pragma unroll
        for (int j = 0; j < 4; j++)
#pragma unroll
            for (int k = 0; k < 4; k++) acc[i][j][k] = 0.f;

    auto load_stage = [&](int k0, int s) {
        uint32_t base = (uint32_t)__cvta_generic_to_shared(sm + (size_t)s * STG);
#pragma unroll
        for (int i = 0; i < 2; i++) {
            int c = tid + 256 * i;
            int row = c >> 2, cc = c & 3;
            uint32_t doff = (uint32_t)(row * ASTR + cc * 8) * 2;
            size_t goff = (size_t)(bm + row) * HID + k0 + cc * 8;
            int szA = (bm + row) < M ? 16 : 0;
            asm volatile("cp.async.ca.shared.global [%0], [%1], 16, %2;\n"
                         :: "r"(base + doff), "l"(Ahi + goff), "r"(szA));
            asm volatile("cp.async.ca.shared.global [%0], [%1], 16, %2;\n"
                         :: "r"(base + AOLO * 2 + doff), "l"(Alo + goff), "r"(szA));
            size_t boff = (size_t)(bn + row) * HID + k0 + cc * 8;
            asm volatile("cp.async.ca.shared.global [%0], [%1], 16;\n"
                         :: "r"(base + AOBH * 2 + doff), "l"(Bhi + boff));
            asm volatile("cp.async.ca.shared.global [%0], [%1], 16;\n"
                         :: "r"(base + AOBL * 2 + doff), "l"(Blo + boff));
        }
        asm volatile("cp.async.commit_group;\n");
    };

    load_stage(0, 0);
    for (int k0i = 0; k0i < 8; k0i++) {
        if (k0i < 7) load_stage((k0i + 1) * 32, (k0i + 1) & 1);
        if (k0i < 7) asm volatile("cp.async.wait_group 1;\n");
        else         asm volatile("cp.async.wait_group 0;\n");
        __syncthreads();

        const __nv_bfloat16* sAhi = sm + (size_t)(k0i & 1) * STG;
        const __nv_bfloat16* sAlo = sAhi + AOLO;
        const __nv_bfloat16* sBhi = sAhi + AOBH;
        const __nv_bfloat16* sBlo = sAhi + AOBL;

#pragma unroll
        for (int ks = 0; ks < 32; ks += 16) {
            uint32_t afh[4][4], afl[4][4], bfh[4][2], bfl[4][2];
#pragma unroll
            for (int mt = 0; mt < 4; mt++) {
                int base = (warp_m * 64 + mt * 16 + g) * ASTR + ks + 2 * t;
                afh[mt][0] = *(const uint32_t*)&sAhi[base];
                afh[mt][1] = *(const uint32_t*)&sAhi[base + 8 * ASTR];
                afh[mt][2] = *(const uint32_t*)&sAhi[base + 8];
                afh[mt][3] = *(const uint32_t*)&sAhi[base + 8 * ASTR + 8];
                afl[mt][0] = *(const uint32_t*)&sAlo[base];
                afl[mt][1] = *(const uint32_t*)&sAlo[base + 8 * ASTR];
                afl[mt][2] = *(const uint32_t*)&sAlo[base + 8];
                afl[mt][3] = *(const uint32_t*)&sAlo[base + 8 * ASTR + 8];
            }
#pragma unroll
            for (int nt = 0; nt < 4; nt++) {
                int base = (warp_n * 32 + nt * 8 + g) * ASTR + ks + 2 * t;
                bfh[nt][0] = *(const uint32_t*)&sBhi[base];
                bfh[nt][1] = *(const uint32_t*)&sBhi[base + 8];
                bfl[nt][0] = *(const uint32_t*)&sBlo[base];
                bfl[nt][1] = *(const uint32_t*)&sBlo[base + 8];
            }
#pragma unroll
            for (int mt = 0; mt < 4; mt++)
#pragma unroll
                for (int nt = 0; nt < 4; nt++) {
                    mma16816(acc[mt][nt], afh[mt], bfh[nt]);
                    mma16816(acc[mt][nt], afh[mt], bfl[nt]);
                    mma16816(acc[mt][nt], afl[mt], bfh[nt]);
                }
        }
        __syncthreads();
    }

#pragma unroll
    for (int mt = 0; mt < 4; mt++) {
        int row = bm + warp_m * 64 + mt * 16 + g;
#pragma unroll
        for (int nt = 0; nt < 4; nt++) {
            int col = bn + warp_n * 32 + nt * 8 + 2 * t;
            if (row < M)
                *(float2*)(C + (size_t)row * HID + col) =
                    make_float2(acc[mt][nt][0], acc[mt][nt][1]);
            if (row + 8 < M)
                *(float2*)(C + (size_t)(row + 8) * HID + col) =
                    make_float2(acc[mt][nt][2], acc[mt][nt][3]);
        }
    }
}

// ---------------- fused per-node finalize/split/prep: warp per node ----------
// h = hn/(dn+eps) [+bias] [relu] -> split bf16 Ahi/Alo
// s = h . ws, d = h . wd (for next layer's attention), if ws != null
// re-zero hzero row, reset mx/dn for next scatter.
__global__ __launch_bounds__(256) void split_nd(
    const float* __restrict__ hn, const float* __restrict__ dnv,
    const float* __restrict__ b, int relu,
    const float* __restrict__ ws, const float* __restrict__ wd,
    __nv_bfloat16* __restrict__ hi, __nv_bfloat16* __restrict__ lo,
    float* __restrict__ s, float* __restrict__ d,
    float* __restrict__ hzero, float* __restrict__ mx, float* __restrict__ dn_out)
{
    int w = (blockIdx.x * blockDim.x + threadIdx.x) >> 5;
    int lane = threadIdx.x & 31;
    if (w >= NN) return;
    float inv = 1.f;
    if (dnv) inv = 1.f / (dnv[w] + 1e-16f);
    const float4* src = (const float4*)hn + (size_t)w * 64;
    float ss = 0.f, dd = 0.f;
#pragma unroll
    for (int i = 0; i < 2; i++) {
        int p = lane + 32 * i;
        float4 v = src[p];
        v.x *= inv; v.y *= inv; v.z *= inv; v.w *= inv;
        if (b) {
            float4 bb = ((const float4*)b)[p];
            v.x += bb.x; v.y += bb.y; v.z += bb.z; v.w += bb.w;
        }
        if (relu) {
            v.x = fmaxf(v.x, 0.f); v.y = fmaxf(v.y, 0.f);
            v.z = fmaxf(v.z, 0.f); v.w = fmaxf(v.w, 0.f);
        }
        if (ws) {
            float4 a = ((const float4*)ws)[p];
            float4 e = ((const float4*)wd)[p];
            ss += v.x * a.x + v.y * a.y + v.z * a.z + v.w * a.w;
            dd += v.x * e.x + v.y * e.y + v.z * e.z + v.w * e.w;
        }
        float vv[4] = {v.x, v.y, v.z, v.w};
        __nv_bfloat16 h4[4], l4[4];
#pragma unroll
        for (int j = 0; j < 4; j++) {
            h4[j] = __float2bfloat16_rn(vv[j]);
            l4[j] = __float2bfloat16_rn(vv[j] - __bfloat162float(h4[j]));
        }
        ((uint2*)hi)[(size_t)w * 64 + p] = *(uint2*)h4;
        ((uint2*)lo)[(size_t)w * 64 + p] = *(uint2*)l4;
    }
    if (hzero) {
        float4 z = make_float4(0.f, 0.f, 0.f, 0.f);
        ((float4*)hzero)[(size_t)w * 64 + lane]      = z;
        ((float4*)hzero)[(size_t)w * 64 + 32 + lane] = z;
    }
    if (ws) {
#pragma unroll
        for (int o = 16; o; o >>= 1) {
            ss += __shfl_xor_sync(~0u, ss, o);
            dd += __shfl_xor_sync(~0u, dd, o);
        }
        if (!lane) {
            s[w] = ss; d[w] = dd;
            mx[w] = -1e30f; dn_out[w] = 0.f;
        }
    }
}

// ---------------- weight-side precompute ----------------
__global__ void split_W(const float* __restrict__ W012, const float* __restrict__ Wc,
                        const float* __restrict__ Wsum,
                        __nv_bfloat16* __restrict__ hi, __nv_bfloat16* __restrict__ lo) {
    int i = blockIdx.x * blockDim.x + threadIdx.x;
    if (i >= 7 * HID * HID) return;
    int slot = i >> 16, r = i & 65535;
    int n = r >> 8, k = r & 255;
    const float* src = (slot == 0) ? W012
                     : (slot <= 5) ? Wc + (size_t)slot * HID * HID
                                   : Wsum;
    float v = src[k * HID + n];
    __nv_bfloat16 h = __float2bfloat16_rn(v);
    hi[i] = h;
    lo[i] = __float2bfloat16_rn(v - __bfloat162float(h));
}

__global__ void wsum_kernel(const float* __restrict__ W3, float* __restrict__ Wsum) {
    int i = blockIdx.x * blockDim.x + threadIdx.x;
    if (i < HID * HID) Wsum[i] = W3[i] + W3[i + HID * HID];
}

// ws[l][k] = Wslot[l][k,:] . a_s[l],  wd likewise (Wslot0 = W012)
__global__ void compute_wsd(const float* __restrict__ W012, const float* __restrict__ Wc,
                            const float* __restrict__ a_s, const float* __restrict__ a_d,
                            float* __restrict__ ws, float* __restrict__ wd) {
    int warp = (blockIdx.x * blockDim.x + threadIdx.x) >> 5;
    int lane = threadIdx.x & 31;
    if (warp >= NL * HID) return;
    int l = warp >> 8, k = warp & 255;
    const float* W = (l == 0) ? W012 : Wc + (size_t)l * HID * HID;
    const float4* row = (const float4*)(W + (size_t)k * HID);
    const float4* as4 = (const float4*)(a_s + (size_t)l * HID);
    const float4* ad4 = (const float4*)(a_d + (size_t)l * HID);
    float ss = 0.f, dd = 0.f;
#pragma unroll
    for (int i = 0; i < 2; i++) {
        int p = lane + 32 * i;
        float4 v = row[p];
        float4 a = as4[p];
        float4 e = ad4[p];
        ss += v.x * a.x + v.y * a.y + v.z * a.z + v.w * a.w;
        dd += v.x * e.x + v.y * e.y + v.z * e.z + v.w * e.w;
    }
#pragma unroll
    for (int o = 16; o; o >>= 1) {
        ss += __shfl_xor_sync(~0u, ss, o);
        dd += __shfl_xor_sync(~0u, dd, o);
    }
    if (!lane) { ws[l * HID + k] = ss; wd[l * HID + k] = dd; }
}

__global__ void compute_Ve(const float* __restrict__ We, const float* __restrict__ a_e,
                           float* __restrict__ Ve) {
    int w = (blockIdx.x * blockDim.x + threadIdx.x) >> 5;
    int lane = threadIdx.x & 31;
    if (w >= NL * EDIM) return;
    int l = w / EDIM, j = w % EDIM;
    const float4* wr = (const float4*)(We + ((size_t)l * EDIM + j) * HID);
    const float4* ar = (const float4*)(a_e + (size_t)l * HID);
    float s = 0.f;
#pragma unroll
    for (int i = 0; i < 2; i++) {
        float4 x = wr[lane + 32 * i];
        float4 y = ar[lane + 32 * i];
        s += x.x * y.x + x.y * y.y + x.z * y.z + x.w * y.w;
    }
#pragma unroll
    for (int o = 16; o; o >>= 1) s += __shfl_xor_sync(~0u, s, o);
    if (!lane) Ve[l * EDIM + j] = s;
}

// edge logits: one warp per 4 consecutive edges — sVe smem reads amortized 4x.
__global__ __launch_bounds__(256) void edge_dots4(const float* __restrict__ edge_attr,
                                                  float* __restrict__ out) {
    __shared__ float4 sVe[NL][EDIM / 4];   // 18 KB
    for (int i = threadIdx.x; i < NL * EDIM / 4; i += blockDim.x)
        ((float4*)sVe)[i] = ((const float4*)g_Ve)[i];
    __syncthreads();
    int w = (blockIdx.x * blockDim.x + threadIdx.x) >> 5;
    int lane = threadIdx.x & 31;
    int e0 = w * 4;
    if (e0 >= NE) return;
    const float4* row = (const float4*)edge_attr;

    float acc[NL][4];
#pragma unroll
    for (int l = 0; l < NL; l++)
#pragma unroll
        for (int j = 0; j < 4; j++) acc[l][j] = 0.f;

#pragma unroll
    for (int i = 0; i < 6; i++) {
        int p = lane + 32 * i;
        float4 v0 = row[(size_t)(e0 + 0) * (EDIM / 4) + p];
        float4 v1 = row[(size_t)(e0 + 1) * (EDIM / 4) + p];
        float4 v2 = row[(size_t)(e0 + 2) * (EDIM / 4) + p];
        float4 v3 = row[(size_t)(e0 + 3) * (EDIM / 4) + p];
#pragma unroll
        for (int l = 0; l < NL; l++) {
            float4 u = sVe[l][p];
            acc[l][0] += v0.x * u.x + v0.y * u.y + v0.z * u.z + v0.w * u.w;
            acc[l][1] += v1.x * u.x + v1.y * u.y + v1.z * u.z + v1.w * u.w;
            acc[l][2] += v2.x * u.x + v2.y * u.y + v2.z * u.z + v2.w * u.w;
            acc[l][3] += v3.x * u.x + v3.y * u.y + v3.z * u.z + v3.w * u.w;
        }
    }
#pragma unroll
    for (int l = 0; l < NL; l++)
#pragma unroll
        for (int j = 0; j < 4; j++) {
            float a = acc[l][j];
#pragma unroll
            for (int o = 16; o; o >>= 1) a += __shfl_xor_sync(~0u, a, o);
            if (!lane) out[(size_t)l * NE + e0 + j] = a;
        }
}

__global__ void alpha_max(const int* __restrict__ ei, const float* __restrict__ s,
                          const float* __restrict__ d, const float* __restrict__ ee,
                          float* __restrict__ alpha, float* __restrict__ mx) {
    int e = blockIdx.x * blockDim.x + threadIdx.x;
    if (e >= NE) return;
    int src = ei[e];
    int dst = ei[NE + e];
    float a = s[src] + d[dst] + ee[e];
    a = a > 0.f ? a : 0.2f * a;
    alpha[e] = a;
    atomicMaxF(&mx[dst], a);
}

// fused: ea = exp(alpha - mx[dst]); dn[dst] += ea; out[dst] += ea * h[src]
__global__ void scatter_ea(const int* __restrict__ ei, const float* __restrict__ h,
                           const float* __restrict__ alpha, const float* __restrict__ mx,
                           float* __restrict__ dn, float* __restrict__ out) {
    int w = (blockIdx.x * blockDim.x + threadIdx.x) >> 5;
    int lane = threadIdx.x & 31;
    if (w >= NE) return;
    int src = ei[w];
    int dst = ei[NE + w];
    float eaV = __expf(alpha[w] - mx[dst]);
    if (!lane) atomicAdd(&dn[dst], eaV);
    const float4* hs = (const float4*)(h + (size_t)src * HID);
    float* ob = out + (size_t)dst * HID;
#pragma unroll
    for (int i = 0; i < 2; i++) {
        int p = lane + 32 * i;
        float4 v = hs[p];
        float x = v.x * eaV, y = v.y * eaV, z = v.z * eaV, u = v.w * eaV;
        asm volatile("red.global.add.v4.f32 [%0], {%1,%2,%3,%4};"
                     :: "l"(ob + p * 4), "f"(x), "f"(y), "f"(z), "f"(u)
                     : "memory");
    }
}

// ---------------- launch ----------------
extern "C" void kernel_launch(void* const* d_in, const int* in_sizes, int n_in,
                              void* d_out, int out_size) {
    const float* x    = (const float*)d_in[0];
    const int*   ei   = (const int*)d_in[1];
    const float* eatt = (const float*)d_in[2];
    const float* W1   = (const float*)d_in[3];
    const float* W2   = (const float*)d_in[4];
    const float* Wc   = (const float*)d_in[5];
    const float* We   = (const float*)d_in[6];
    const float* a_s  = (const float*)d_in[7];
    const float* a_d  = (const float*)d_in[8];
    const float* a_e  = (const float*)d_in[9];
    const float* bias = (const float*)d_in[10];
    const float* W3   = (const float*)d_in[11];
    float*       out  = (float*)d_out;

    float *p_hl, *p_hn, *p_ee, *p_ea, *p_s, *p_d, *p_mx, *p_dn, *p_Ve;
    float *p_ws, *p_wd, *p_W12, *p_W012, *p_Ws;
    __nv_bfloat16 *p_Ahi, *p_Alo, *p_Bthi, *p_Btlo;
    cudaGetSymbolAddress((void**)&p_hl, g_hl);
    cudaGetSymbolAddress((void**)&p_hn, g_hn);
    cudaGetSymbolAddress((void**)&p_ee, g_ee);
    cudaGetSymbolAddress((void**)&p_ea, g_ea);
    cudaGetSymbolAddress((void**)&p_s, g_s);
    cudaGetSymbolAddress((void**)&p_d, g_d);
    cudaGetSymbolAddress((void**)&p_mx, g_mx);
    cudaGetSymbolAddress((void**)&p_dn, g_dn);
    cudaGetSymbolAddress((void**)&p_Ve, g_Ve);
    cudaGetSymbolAddress((void**)&p_ws, g_ws);
    cudaGetSymbolAddress((void**)&p_wd, g_wd);
    cudaGetSymbolAddress((void**)&p_W12, g_W12);
    cudaGetSymbolAddress((void**)&p_W012, g_W012);
    cudaGetSymbolAddress((void**)&p_Ws, g_Wsum);
    cudaGetSymbolAddress((void**)&p_Ahi, g_Ahi);
    cudaGetSymbolAddress((void**)&p_Alo, g_Alo);
    cudaGetSymbolAddress((void**)&p_Bthi, g_Bthi);
    cudaGetSymbolAddress((void**)&p_Btlo, g_Btlo);

    cudaFuncSetAttribute(mma_gemm2, cudaFuncAttributeMaxDynamicSharedMemorySize,
                         2 * STG * (int)sizeof(__nv_bfloat16));
    const size_t smem_sz = 2 * STG * sizeof(__nv_bfloat16);

    const int MBY = (NN + 127) / 128;
    const dim3 gemm_grid(2, MBY);
    const int NODE_W = (NN * 32 + 255) / 256;

    // ---- one-time precompute ----
    sgemm128<<<dim3(2, 2), 256>>>(W1, W2, p_W12, HID);
    sgemm128<<<dim3(2, 2), 256>>>(p_W12, Wc, p_W012, HID);
    wsum_kernel<<<(HID * HID + 255) / 256, 256>>>(W3, p_Ws);
    split_W<<<(7 * HID * HID + 255) / 256, 256>>>(p_W012, Wc, p_Ws, p_Bthi, p_Btlo);
    compute_wsd<<<(NL * HID * 32 + 255) / 256, 256>>>(p_W012, Wc, a_s, a_d, p_ws, p_wd);
    compute_Ve<<<(NL * EDIM * 32 + 255) / 256, 256>>>(We, a_e, p_Ve);
    edge_dots4<<<((NE / 4) * 32 + 255) / 256, 256>>>(eatt, p_ee);

    // initial: A = split(x); s,d for layer 0; zero hn; init mx/dn
    split_nd<<<NODE_W, 256>>>(x, nullptr, nullptr, 0, p_ws, p_wd,
                              p_Ahi, p_Alo, p_s, p_d, p_hn, p_mx, p_dn);

    for (int l = 0; l < NL; l++) {
        mma_gemm2<<<gemm_grid, 256, smem_sz>>>(
            p_Ahi, p_Alo,
            p_Bthi + (size_t)l * HID * HID, p_Btlo + (size_t)l * HID * HID,
            p_hl, NN);
        alpha_max<<<(NE + 255) / 256, 256>>>(ei, p_s, p_d, p_ee + (size_t)l * NE,
                                             p_ea, p_mx);
        scatter_ea<<<(NE * 32 + 255) / 256, 256>>>(ei, p_hl, p_ea, p_mx, p_dn, p_hn);
        // finalize layer l; prepare s,d/mx/dn/hn for layer l+1 (skip attn prep after last)
        int last = (l == NL - 1);
        split_nd<<<NODE_W, 256>>>(p_hn, p_dn, bias + (size_t)l * HID, last,
                                  last ? nullptr : p_ws + (size_t)(l + 1) * HID,
                                  last ? nullptr : p_wd + (size_t)(l + 1) * HID,
                                  p_Ahi, p_Alo, p_s, p_d,
                                  last ? nullptr : p_hn, p_mx, p_dn);
    }

    // out = relu(h) @ (W3a + W3b)
    mma_gemm2<<<gemm_grid, 256, smem_sz>>>(
        p_Ahi, p_Alo,
        p_Bthi + (size_t)6 * HID * HID, p_Btlo + (size_t)6 * HID * HID,
        out, NN);
}